// round 3
// baseline (speedup 1.0000x reference)
#include <cuda_runtime.h>
#include <math.h>

// Problem constants (from reference): N=50000, E=800000, F1=96, F2=64
#define MAXN 50000
#define MAXE 800000
#define F1 96
#define F2 64

// Scratch (device globals; no allocation allowed).
// __align__(16) REQUIRED: targets of red.global.add.v4.f32 / float4 accesses.
__device__ __align__(16) float g_agg1[MAXN * F1];   // sum of x[src] per dst
__device__ __align__(16) float g_cnt [MAXN];        // in-degree per dst
__device__ __align__(16) float g_h   [MAXN * F1];   // layer-1 output
__device__ __align__(16) float g_y2  [MAXN * F2];   // h @ w2_r^T (pre-agg messages)
__device__ __align__(16) float g_agg2[MAXN * F2];   // sum of y2[src] per dst

// ---------------------------------------------------------------------------
// Zero the accumulators
// ---------------------------------------------------------------------------
__global__ void zero_all_kernel() {
    long long i = (long long)blockIdx.x * blockDim.x + threadIdx.x;
    long long stride = (long long)gridDim.x * blockDim.x;
    const long long n1 = (long long)MAXN * F1;
    const long long n2 = (long long)MAXN * F2;
    for (long long t = i; t < n1; t += stride) g_agg1[t] = 0.0f;
    for (long long t = i; t < n2; t += stride) g_agg2[t] = 0.0f;
    for (long long t = i; t < MAXN; t += stride) g_cnt[t] = 0.0f;
}

// ---------------------------------------------------------------------------
// Vector reduction (no-return scatter-add), sm_90+
// ---------------------------------------------------------------------------
__device__ __forceinline__ void red_add_v4(float* p, float4 v) {
    asm volatile("red.global.add.v4.f32 [%0], {%1, %2, %3, %4};"
                 :: "l"(p), "f"(v.x), "f"(v.y), "f"(v.z), "f"(v.w)
                 : "memory");
}

// ---------------------------------------------------------------------------
// Edge aggregation, layer 1: agg1[dst] += x[src] (96 floats = 24 float4),
// plus in-degree count. One thread per (edge, float4-chunk).
// edge_index is INT32 (JAX x64-disabled downgrades int64 -> int32).
// ---------------------------------------------------------------------------
__global__ void agg1_kernel(const float4* __restrict__ x4,
                            const int* __restrict__ src,
                            const int* __restrict__ dst,
                            int e) {
    long long idx = (long long)blockIdx.x * blockDim.x + threadIdx.x;
    const long long total = (long long)e * 24;
    if (idx >= total) return;
    int ed = (int)(idx / 24);
    int c  = (int)(idx % 24);
    int s = src[ed];
    int d = dst[ed];
    float4 v = x4[(long long)s * 24 + c];
    red_add_v4(&g_agg1[(long long)d * F1 + c * 4], v);
    if (c == 0) atomicAdd(&g_cnt[d], 1.0f);
}

// ---------------------------------------------------------------------------
// Layer 1: h = elu(x @ w1_l^T + b1 + (agg1/cnt) @ w1_r^T)
// Block: (96, 3) threads, 12 nodes/block, 4 nodes per thread (register tile).
// Weights transposed into SMEM: swl[k*96+f] -> conflict-free (f contiguous).
// ---------------------------------------------------------------------------
__global__ void layer1_kernel(const float* __restrict__ x,
                              const float* __restrict__ wl,
                              const float* __restrict__ bl,
                              const float* __restrict__ wr,
                              int n) {
    extern __shared__ float smem[];
    float* swl = smem;              // [96][96] transposed: swl[k*96+f] = wl[f*96+k]
    float* swr = smem + F1 * F1;
    __shared__ float sb[F1];

    const int f   = threadIdx.x;             // 0..95 (output feature)
    const int tid = threadIdx.y * F1 + f;    // 0..287
    for (int i = tid; i < F1 * F1; i += 288) {
        int fo = i / F1, k = i % F1;
        swl[k * F1 + fo] = wl[i];
        swr[k * F1 + fo] = wr[i];
    }
    if (tid < F1) sb[tid] = bl[tid];
    __syncthreads();

    const int base = blockIdx.x * 12 + threadIdx.y * 4;
    int n0 = base + 0, n1_ = base + 1, n2_ = base + 2, n3_ = base + 3;
    bool v0 = n0 < n, v1 = n1_ < n, v2 = n2_ < n, v3 = n3_ < n;
    int c0 = v0 ? n0 : 0, c1 = v1 ? n1_ : 0, c2 = v2 ? n2_ : 0, c3 = v3 ? n3_ : 0;

    const float* xp0 = x + (long long)c0 * F1;
    const float* xp1 = x + (long long)c1 * F1;
    const float* xp2 = x + (long long)c2 * F1;
    const float* xp3 = x + (long long)c3 * F1;
    const float* ap0 = g_agg1 + (long long)c0 * F1;
    const float* ap1 = g_agg1 + (long long)c1 * F1;
    const float* ap2 = g_agg1 + (long long)c2 * F1;
    const float* ap3 = g_agg1 + (long long)c3 * F1;
    float inv0 = 1.0f / fmaxf(g_cnt[c0], 1.0f);
    float inv1 = 1.0f / fmaxf(g_cnt[c1], 1.0f);
    float inv2 = 1.0f / fmaxf(g_cnt[c2], 1.0f);
    float inv3 = 1.0f / fmaxf(g_cnt[c3], 1.0f);

    float a0 = 0.f, a1 = 0.f, a2 = 0.f, a3 = 0.f;
    #pragma unroll 4
    for (int k = 0; k < F1; k++) {
        float wa = swl[k * F1 + f];
        float wb = swr[k * F1 + f];
        a0 += wa * xp0[k] + wb * (ap0[k] * inv0);
        a1 += wa * xp1[k] + wb * (ap1[k] * inv1);
        a2 += wa * xp2[k] + wb * (ap2[k] * inv2);
        a3 += wa * xp3[k] + wb * (ap3[k] * inv3);
    }
    float bias = sb[f];
    if (v0) { float v = a0 + bias; g_h[(long long)n0  * F1 + f] = v > 0.f ? v : (expf(v) - 1.0f); }
    if (v1) { float v = a1 + bias; g_h[(long long)n1_ * F1 + f] = v > 0.f ? v : (expf(v) - 1.0f); }
    if (v2) { float v = a2 + bias; g_h[(long long)n2_ * F1 + f] = v > 0.f ? v : (expf(v) - 1.0f); }
    if (v3) { float v = a3 + bias; g_h[(long long)n3_ * F1 + f] = v > 0.f ? v : (expf(v) - 1.0f); }
}

// ---------------------------------------------------------------------------
// Layer 2 GEMMs (fused): out_partial = h @ w2_l^T + b2 ; y2 = h @ w2_r^T
// Block: (64, 4) threads, 16 nodes/block, 4 nodes/thread, two accumulators
// per node so each h load feeds 2 FMAs.
// ---------------------------------------------------------------------------
__global__ void layer2_kernel(const float* __restrict__ wl,
                              const float* __restrict__ bl,
                              const float* __restrict__ wr,
                              float* __restrict__ out,
                              int n) {
    extern __shared__ float smem[];
    float* swl = smem;              // [96][64] transposed: swl[k*64+f] = wl[f*96+k]
    float* swr = smem + F1 * F2;
    __shared__ float sb[F2];

    const int f   = threadIdx.x;             // 0..63
    const int tid = threadIdx.y * F2 + f;    // 0..255
    for (int i = tid; i < F2 * F1; i += 256) {
        int fo = i / F1, k = i % F1;
        swl[k * F2 + fo] = wl[i];
        swr[k * F2 + fo] = wr[i];
    }
    if (tid < F2) sb[tid] = bl[tid];
    __syncthreads();

    const int base = blockIdx.x * 16 + threadIdx.y * 4;
    int n0 = base + 0, n1_ = base + 1, n2_ = base + 2, n3_ = base + 3;
    bool v0 = n0 < n, v1 = n1_ < n, v2 = n2_ < n, v3 = n3_ < n;
    int c0 = v0 ? n0 : 0, c1 = v1 ? n1_ : 0, c2 = v2 ? n2_ : 0, c3 = v3 ? n3_ : 0;

    const float* hp0 = g_h + (long long)c0 * F1;
    const float* hp1 = g_h + (long long)c1 * F1;
    const float* hp2 = g_h + (long long)c2 * F1;
    const float* hp3 = g_h + (long long)c3 * F1;

    float l0 = 0.f, l1 = 0.f, l2 = 0.f, l3 = 0.f;
    float r0 = 0.f, r1 = 0.f, r2 = 0.f, r3 = 0.f;
    #pragma unroll 4
    for (int k = 0; k < F1; k++) {
        float wa = swl[k * F2 + f];
        float wb = swr[k * F2 + f];
        float h0 = hp0[k], h1 = hp1[k], h2 = hp2[k], h3 = hp3[k];
        l0 += wa * h0; r0 += wb * h0;
        l1 += wa * h1; r1 += wb * h1;
        l2 += wa * h2; r2 += wb * h2;
        l3 += wa * h3; r3 += wb * h3;
    }
    float bias = sb[f];
    if (v0) { out[(long long)n0  * F2 + f] = l0 + bias; g_y2[(long long)n0  * F2 + f] = r0; }
    if (v1) { out[(long long)n1_ * F2 + f] = l1 + bias; g_y2[(long long)n1_ * F2 + f] = r1; }
    if (v2) { out[(long long)n2_ * F2 + f] = l2 + bias; g_y2[(long long)n2_ * F2 + f] = r2; }
    if (v3) { out[(long long)n3_ * F2 + f] = l3 + bias; g_y2[(long long)n3_ * F2 + f] = r3; }
}

// ---------------------------------------------------------------------------
// Edge aggregation, layer 2: agg2[dst] += y2[src] (64 floats = 16 float4)
// ---------------------------------------------------------------------------
__global__ void agg2_kernel(const int* __restrict__ src,
                            const int* __restrict__ dst,
                            int e) {
    long long idx = (long long)blockIdx.x * blockDim.x + threadIdx.x;
    const long long total = (long long)e * 16;
    if (idx >= total) return;
    int ed = (int)(idx / 16);
    int c  = (int)(idx % 16);
    int s = src[ed];
    int d = dst[ed];
    const float4* y4 = (const float4*)g_y2;
    float4 v = y4[(long long)s * 16 + c];
    red_add_v4(&g_agg2[(long long)d * F2 + c * 4], v);
}

// ---------------------------------------------------------------------------
// Final: out += agg2 / max(cnt, 1)
// ---------------------------------------------------------------------------
__global__ void final_kernel(float* __restrict__ out, int n) {
    long long idx = (long long)blockIdx.x * blockDim.x + threadIdx.x;
    const long long total = (long long)n * 16;   // n * 64 floats / 4
    if (idx >= total) return;
    int node = (int)(idx / 16);
    float inv = 1.0f / fmaxf(g_cnt[node], 1.0f);
    float4* o4 = (float4*)out;
    const float4* a4 = (const float4*)g_agg2;
    float4 o = o4[idx];
    float4 a = a4[idx];
    o.x += a.x * inv; o.y += a.y * inv; o.z += a.z * inv; o.w += a.w * inv;
    o4[idx] = o;
}

// ---------------------------------------------------------------------------
// Launch
// ---------------------------------------------------------------------------
extern "C" void kernel_launch(void* const* d_in, const int* in_sizes, int n_in,
                              void* d_out, int out_size) {
    const float* x   = (const float*)d_in[0];
    const int*   ei  = (const int*)d_in[1];   // [2, E] int32 (JAX downgrades int64)
    const float* w1l = (const float*)d_in[2];
    const float* b1l = (const float*)d_in[3];
    const float* w1r = (const float*)d_in[4];
    const float* w2l = (const float*)d_in[5];
    const float* b2l = (const float*)d_in[6];
    const float* w2r = (const float*)d_in[7];
    float* out = (float*)d_out;

    const int n = in_sizes[0] / F1;
    const int e = in_sizes[1] / 2;
    const int* src = ei;
    const int* dst = ei + e;

    // Opt-in SMEM (layer1 needs 73728B > 48KB default; layer2 exactly 48KB).
    cudaFuncSetAttribute(layer1_kernel, cudaFuncAttributeMaxDynamicSharedMemorySize,
                         F1 * F1 * 2 * (int)sizeof(float));
    cudaFuncSetAttribute(layer2_kernel, cudaFuncAttributeMaxDynamicSharedMemorySize,
                         F1 * F2 * 2 * (int)sizeof(float));

    zero_all_kernel<<<2048, 256>>>();

    {   // layer-1 aggregation: E*24 threads
        long long tot = (long long)e * 24;
        int blocks = (int)((tot + 255) / 256);
        agg1_kernel<<<blocks, 256>>>((const float4*)x, src, dst, e);
    }

    layer1_kernel<<<(n + 11) / 12, dim3(96, 3), F1 * F1 * 2 * sizeof(float)>>>(
        x, w1l, b1l, w1r, n);

    layer2_kernel<<<(n + 15) / 16, dim3(64, 4), F1 * F2 * 2 * sizeof(float)>>>(
        w2l, b2l, w2r, out, n);

    {   // layer-2 aggregation: E*16 threads
        long long tot = (long long)e * 16;
        int blocks = (int)((tot + 255) / 256);
        agg2_kernel<<<blocks, 256>>>(src, dst, e);
    }

    {   // final combine: N*16 float4
        long long tot = (long long)n * 16;
        int blocks = (int)((tot + 255) / 256);
        final_kernel<<<blocks, 256>>>(out, n);
    }
}

// round 4
// speedup vs baseline: 2.7323x; 2.7323x over previous
#include <cuda_runtime.h>
#include <math.h>

// Problem constants: N=50000, E=800000, F1=96, F2=64
#define MAXN 50000
#define F1 96
#define F2 64

// Scratch (device globals). __align__(16) required for v4 RED / float4.
__device__ __align__(16) float g_agg1[MAXN * F1];
__device__ __align__(16) float g_cnt [MAXN];
__device__ __align__(16) float g_h   [MAXN * F1];
__device__ __align__(16) float g_y2  [MAXN * F2];
__device__ __align__(16) float g_agg2[MAXN * F2];

// ---------------------------------------------------------------------------
__global__ void zero_all_kernel() {
    long long i = (long long)blockIdx.x * blockDim.x + threadIdx.x;
    long long stride = (long long)gridDim.x * blockDim.x;
    const long long n1 = (long long)MAXN * F1;
    const long long n2 = (long long)MAXN * F2;
    for (long long t = i; t < n1; t += stride) g_agg1[t] = 0.0f;
    for (long long t = i; t < n2; t += stride) g_agg2[t] = 0.0f;
    for (long long t = i; t < MAXN; t += stride) g_cnt[t] = 0.0f;
}

__device__ __forceinline__ void red_add_v4(float* p, float4 v) {
    asm volatile("red.global.add.v4.f32 [%0], {%1, %2, %3, %4};"
                 :: "l"(p), "f"(v.x), "f"(v.y), "f"(v.z), "f"(v.w)
                 : "memory");
}

// ---------------------------------------------------------------------------
// agg1: agg1[dst] += x[src] (24 float4/edge) + in-degree
// ---------------------------------------------------------------------------
__global__ void agg1_kernel(const float4* __restrict__ x4,
                            const int* __restrict__ src,
                            const int* __restrict__ dst,
                            int e) {
    long long idx = (long long)blockIdx.x * blockDim.x + threadIdx.x;
    const long long total = (long long)e * 24;
    if (idx >= total) return;
    int ed = (int)(idx / 24);
    int c  = (int)(idx % 24);
    int s = src[ed];
    int d = dst[ed];
    float4 v = x4[(long long)s * 24 + c];
    red_add_v4(&g_agg1[(long long)d * F1 + c * 4], v);
    if (c == 0) atomicAdd(&g_cnt[d], 1.0f);
}

// ---------------------------------------------------------------------------
// Layer 1: h = elu(x @ w1_l^T + b1 + (agg1/cnt) @ w1_r^T)
// Block: (24,8) = 192 threads; thread tile = 4 features x 4 nodes; 32 nodes/tile.
// Weights loaded ONCE per block (transposed, conflict-free), grid-stride tiles.
// Mean-divide folded out of the inner loop (separate l/r accumulators).
// ---------------------------------------------------------------------------
#define L1_TN 32   // nodes per tile
__global__ void layer1_kernel(const float* __restrict__ x,
                              const float* __restrict__ wl,
                              const float* __restrict__ bl,
                              const float* __restrict__ wr,
                              int n) {
    extern __shared__ float smem[];
    float* swl = smem;                     // [96][96]: swl[k*96+f] = wl[f*96+k]
    float* swr = swl + F1 * F1;            // [96][96]
    float* sx  = swr + F1 * F1;            // [32][96] node-major x tile
    float* sm  = sx  + L1_TN * F1;         // [32][96] node-major agg tile
    float* sinv= sm  + L1_TN * F1;         // [32]
    float* sb  = sinv + L1_TN;             // [96]

    const int tx = threadIdx.x;            // 0..23 (feature groups of 4)
    const int ty = threadIdx.y;            // 0..7  (node groups of 4)
    const int tid = ty * 24 + tx;          // 0..191
    const int f0 = tx * 4;
    const int nn0 = ty * 4;

    for (int i = tid; i < F1 * F1; i += 192) {
        int fo = i / F1, k = i % F1;
        float a = wl[i], b = wr[i];
        swl[k * F1 + fo] = a;
        swr[k * F1 + fo] = b;
    }
    if (tid < F1) sb[tid] = bl[tid];

    const int ntiles = (n + L1_TN - 1) / L1_TN;
    for (int t = blockIdx.x; t < ntiles; t += gridDim.x) {
        const int base = t * L1_TN;
        __syncthreads();   // previous iteration's readers are done

        // stage x & agg tiles (float4 coalesced); 32*24 float4 each
        for (int i = tid; i < L1_TN * 24; i += 192) {
            int node = i / 24, c = i % 24;
            int g = base + node;
            float4 vx = make_float4(0.f,0.f,0.f,0.f);
            float4 vm = vx;
            if (g < n) {
                vx = ((const float4*)x)[(long long)g * 24 + c];
                vm = ((const float4*)g_agg1)[(long long)g * 24 + c];
            }
            ((float4*)sx)[node * 24 + c] = vx;
            ((float4*)sm)[node * 24 + c] = vm;
        }
        if (tid < L1_TN) {
            int g = base + tid;
            sinv[tid] = (g < n) ? 1.0f / fmaxf(g_cnt[g], 1.0f) : 0.0f;
        }
        __syncthreads();

        float l[4][4], r[4][4];
        #pragma unroll
        for (int i = 0; i < 4; i++)
            #pragma unroll
            for (int j = 0; j < 4; j++) { l[i][j] = 0.f; r[i][j] = 0.f; }

        #pragma unroll 2
        for (int k = 0; k < F1; k++) {
            float wa0 = swl[k * F1 + f0 + 0];
            float wa1 = swl[k * F1 + f0 + 1];
            float wa2 = swl[k * F1 + f0 + 2];
            float wa3 = swl[k * F1 + f0 + 3];
            float wb0 = swr[k * F1 + f0 + 0];
            float wb1 = swr[k * F1 + f0 + 1];
            float wb2 = swr[k * F1 + f0 + 2];
            float wb3 = swr[k * F1 + f0 + 3];
            #pragma unroll
            for (int j = 0; j < 4; j++) {
                float xv = sx[(nn0 + j) * F1 + k];
                float mv = sm[(nn0 + j) * F1 + k];
                l[0][j] += wa0 * xv; r[0][j] += wb0 * mv;
                l[1][j] += wa1 * xv; r[1][j] += wb1 * mv;
                l[2][j] += wa2 * xv; r[2][j] += wb2 * mv;
                l[3][j] += wa3 * xv; r[3][j] += wb3 * mv;
            }
        }

        float b0 = sb[f0+0], b1 = sb[f0+1], b2 = sb[f0+2], b3 = sb[f0+3];
        #pragma unroll
        for (int j = 0; j < 4; j++) {
            int g = base + nn0 + j;
            if (g >= n) continue;
            float inv = sinv[nn0 + j];
            float4 o;
            o.x = l[0][j] + inv * r[0][j] + b0;
            o.y = l[1][j] + inv * r[1][j] + b1;
            o.z = l[2][j] + inv * r[2][j] + b2;
            o.w = l[3][j] + inv * r[3][j] + b3;
            o.x = o.x > 0.f ? o.x : (expf(o.x) - 1.0f);
            o.y = o.y > 0.f ? o.y : (expf(o.y) - 1.0f);
            o.z = o.z > 0.f ? o.z : (expf(o.z) - 1.0f);
            o.w = o.w > 0.f ? o.w : (expf(o.w) - 1.0f);
            ((float4*)g_h)[((long long)g * F1 + f0) >> 2] = o;
        }
    }
}

// ---------------------------------------------------------------------------
// Layer 2 (fused dual GEMM): out = h @ w2_l^T + b2 ; y2 = h @ w2_r^T
// Block: (16,16) = 256 threads; 4 features x 4 nodes per thread; 64 nodes/tile.
// ---------------------------------------------------------------------------
#define L2_TN 64   // nodes per tile
__global__ void layer2_kernel(const float* __restrict__ wl,
                              const float* __restrict__ bl,
                              const float* __restrict__ wr,
                              float* __restrict__ out,
                              int n) {
    extern __shared__ float smem[];
    float* swl = smem;                     // [96][64]: swl[k*64+f] = wl[f*96+k]
    float* swr = swl + F1 * F2;
    float* sh  = swr + F1 * F2;            // [64][96] node-major h tile
    float* sb  = sh  + L2_TN * F1;         // [64]

    const int tx = threadIdx.x;            // 0..15 (feature groups of 4)
    const int ty = threadIdx.y;            // 0..15 (node groups of 4)
    const int tid = ty * 16 + tx;          // 0..255
    const int f0 = tx * 4;
    const int nn0 = ty * 4;

    for (int i = tid; i < F2 * F1; i += 256) {
        int fo = i / F1, k = i % F1;
        swl[k * F2 + fo] = wl[i];
        swr[k * F2 + fo] = wr[i];
    }
    if (tid < F2) sb[tid] = bl[tid];

    const int ntiles = (n + L2_TN - 1) / L2_TN;
    for (int t = blockIdx.x; t < ntiles; t += gridDim.x) {
        const int base = t * L2_TN;
        __syncthreads();

        // stage h tile: 64*24 float4
        for (int i = tid; i < L2_TN * 24; i += 256) {
            int node = i / 24, c = i % 24;
            int g = base + node;
            float4 v = make_float4(0.f,0.f,0.f,0.f);
            if (g < n) v = ((const float4*)g_h)[(long long)g * 24 + c];
            ((float4*)sh)[node * 24 + c] = v;
        }
        __syncthreads();

        float l[4][4], r[4][4];
        #pragma unroll
        for (int i = 0; i < 4; i++)
            #pragma unroll
            for (int j = 0; j < 4; j++) { l[i][j] = 0.f; r[i][j] = 0.f; }

        #pragma unroll 2
        for (int k = 0; k < F1; k++) {
            float wa0 = swl[k * F2 + f0 + 0];
            float wa1 = swl[k * F2 + f0 + 1];
            float wa2 = swl[k * F2 + f0 + 2];
            float wa3 = swl[k * F2 + f0 + 3];
            float wb0 = swr[k * F2 + f0 + 0];
            float wb1 = swr[k * F2 + f0 + 1];
            float wb2 = swr[k * F2 + f0 + 2];
            float wb3 = swr[k * F2 + f0 + 3];
            #pragma unroll
            for (int j = 0; j < 4; j++) {
                float hv = sh[(nn0 + j) * F1 + k];
                l[0][j] += wa0 * hv; r[0][j] += wb0 * hv;
                l[1][j] += wa1 * hv; r[1][j] += wb1 * hv;
                l[2][j] += wa2 * hv; r[2][j] += wb2 * hv;
                l[3][j] += wa3 * hv; r[3][j] += wb3 * hv;
            }
        }

        float b0 = sb[f0+0], b1 = sb[f0+1], b2 = sb[f0+2], b3 = sb[f0+3];
        #pragma unroll
        for (int j = 0; j < 4; j++) {
            int g = base + nn0 + j;
            if (g >= n) continue;
            float4 o, y;
            o.x = l[0][j] + b0; y.x = r[0][j];
            o.y = l[1][j] + b1; y.y = r[1][j];
            o.z = l[2][j] + b2; y.z = r[2][j];
            o.w = l[3][j] + b3; y.w = r[3][j];
            ((float4*)out)  [((long long)g * F2 + f0) >> 2] = o;
            ((float4*)g_y2)[((long long)g * F2 + f0) >> 2] = y;
        }
    }
}

// ---------------------------------------------------------------------------
// agg2: agg2[dst] += y2[src] (16 float4/edge)
// ---------------------------------------------------------------------------
__global__ void agg2_kernel(const int* __restrict__ src,
                            const int* __restrict__ dst,
                            int e) {
    long long idx = (long long)blockIdx.x * blockDim.x + threadIdx.x;
    const long long total = (long long)e * 16;
    if (idx >= total) return;
    int ed = (int)(idx / 16);
    int c  = (int)(idx % 16);
    int s = src[ed];
    int d = dst[ed];
    const float4* y4 = (const float4*)g_y2;
    float4 v = y4[(long long)s * 16 + c];
    red_add_v4(&g_agg2[(long long)d * F2 + c * 4], v);
}

// ---------------------------------------------------------------------------
// Final: out += agg2 / max(cnt, 1)
// ---------------------------------------------------------------------------
__global__ void final_kernel(float* __restrict__ out, int n) {
    long long idx = (long long)blockIdx.x * blockDim.x + threadIdx.x;
    const long long total = (long long)n * 16;
    if (idx >= total) return;
    int node = (int)(idx / 16);
    float inv = 1.0f / fmaxf(g_cnt[node], 1.0f);
    float4* o4 = (float4*)out;
    const float4* a4 = (const float4*)g_agg2;
    float4 o = o4[idx];
    float4 a = a4[idx];
    o.x += a.x * inv; o.y += a.y * inv; o.z += a.z * inv; o.w += a.w * inv;
    o4[idx] = o;
}

// ---------------------------------------------------------------------------
extern "C" void kernel_launch(void* const* d_in, const int* in_sizes, int n_in,
                              void* d_out, int out_size) {
    const float* x   = (const float*)d_in[0];
    const int*   ei  = (const int*)d_in[1];   // [2, E] int32
    const float* w1l = (const float*)d_in[2];
    const float* b1l = (const float*)d_in[3];
    const float* w1r = (const float*)d_in[4];
    const float* w2l = (const float*)d_in[5];
    const float* b2l = (const float*)d_in[6];
    const float* w2r = (const float*)d_in[7];
    float* out = (float*)d_out;

    const int n = in_sizes[0] / F1;
    const int e = in_sizes[1] / 2;
    const int* src = ei;
    const int* dst = ei + e;

    const int l1_smem = (2 * F1 * F1 + 2 * L1_TN * F1 + L1_TN + F1) * (int)sizeof(float);
    const int l2_smem = (2 * F1 * F2 + L2_TN * F1 + F2) * (int)sizeof(float);
    cudaFuncSetAttribute(layer1_kernel, cudaFuncAttributeMaxDynamicSharedMemorySize, l1_smem);
    cudaFuncSetAttribute(layer2_kernel, cudaFuncAttributeMaxDynamicSharedMemorySize, l2_smem);

    zero_all_kernel<<<2048, 256>>>();

    {   // layer-1 aggregation
        long long tot = (long long)e * 24;
        int blocks = (int)((tot + 255) / 256);
        agg1_kernel<<<blocks, 256>>>((const float4*)x, src, dst, e);
    }

    {   // layer 1: 2 blocks/SM resident, grid-stride
        int ntiles = (n + L1_TN - 1) / L1_TN;
        int grid = ntiles < 296 ? ntiles : 296;
        layer1_kernel<<<grid, dim3(24, 8), l1_smem>>>(x, w1l, b1l, w1r, n);
    }

    {   // layer 2: 3 blocks/SM resident
        int ntiles = (n + L2_TN - 1) / L2_TN;
        int grid = ntiles < 444 ? ntiles : 444;
        layer2_kernel<<<grid, dim3(16, 16), l2_smem>>>(w2l, b2l, w2r, out, n);
    }

    {   // layer-2 aggregation
        long long tot = (long long)e * 16;
        int blocks = (int)((tot + 255) / 256);
        agg2_kernel<<<blocks, 256>>>(src, dst, e);
    }

    {   // final combine
        long long tot = (long long)n * 16;
        int blocks = (int)((tot + 255) / 256);
        final_kernel<<<blocks, 256>>>(out, n);
    }
}